// round 1
// baseline (speedup 1.0000x reference)
#include <cuda_runtime.h>

// RNN_26938034880941: vanilla tanh RNN
//   B=4096, S=512, I=1, H=16, O=1
// Mapping: 16 threads per batch element (one hidden unit per thread),
// 2 batches per warp, 8 batches per 128-thread block, grid = 512 blocks.
// h exchanged via ping-pong shared buffer + __syncwarp per step.
// Dot product via packed fma.rn.f32x2 (FFMA2). tanh via ex2/rcp (error ~1e-6).
// x prefetched in 64-step chunks, double-buffered through shared memory.

#define TWO_LOG2E 2.88539008177792681472f  // 2*log2(e)

__device__ __forceinline__ unsigned long long pack2(float a, float b) {
    unsigned long long r;
    asm("mov.b64 %0, {%1, %2};" : "=l"(r) : "f"(a), "f"(b));
    return r;
}
__device__ __forceinline__ unsigned long long fma2(unsigned long long a,
                                                   unsigned long long b,
                                                   unsigned long long c) {
    unsigned long long d;
    asm("fma.rn.f32x2 %0, %1, %2, %3;" : "=l"(d) : "l"(a), "l"(b), "l"(c));
    return d;
}
__device__ __forceinline__ unsigned long long mul2(unsigned long long a,
                                                   unsigned long long b) {
    unsigned long long d;
    asm("mul.rn.f32x2 %0, %1, %2;" : "=l"(d) : "l"(a), "l"(b));
    return d;
}
__device__ __forceinline__ unsigned long long add2(unsigned long long a,
                                                   unsigned long long b) {
    unsigned long long d;
    asm("add.rn.f32x2 %0, %1, %2;" : "=l"(d) : "l"(a), "l"(b));
    return d;
}
__device__ __forceinline__ float hsum2(unsigned long long a) {
    float lo, hi;
    asm("mov.b64 {%0, %1}, %2;" : "=f"(lo), "=f"(hi) : "l"(a));
    return lo + hi;
}
// tanh(z) = 1 - 2/(exp(2z)+1). ex2/rcp approx: abs error ~1e-6, robust at +-inf.
__device__ __forceinline__ float tanh_fast(float z) {
    float q = z * TWO_LOG2E;
    float e;
    asm("ex2.approx.f32 %0, %1;" : "=f"(e) : "f"(q));
    float d = e + 1.0f;
    float r;
    asm("rcp.approx.f32 %0, %1;" : "=f"(r) : "f"(d));
    return fmaf(-2.0f, r, 1.0f);
}

__global__ void __launch_bounds__(128)
rnn_kernel(const float* __restrict__ x,     // [4096,512,1]
           const float* __restrict__ Wih,   // [16,1]
           const float* __restrict__ Whh,   // [16,16]
           const float* __restrict__ bih,   // [16]
           const float* __restrict__ bhh,   // [16]
           const float* __restrict__ Wfc,   // [1,16]
           const float* __restrict__ bfc,   // [1]
           float* __restrict__ out)         // [4096,1]
{
    // 8 batches per block: ping-pong h (16 floats each), double-buffered x chunk (64 floats)
    __shared__ __align__(16) float hbuf[8][2][16];
    __shared__ __align__(16) float xbuf[8][2][64];

    const int tid  = threadIdx.x;
    const int lane = tid & 31;
    const int warp = tid >> 5;
    const int g    = lane >> 4;   // batch within warp (0/1)
    const int j    = lane & 15;   // hidden unit owned by this thread
    const int bib  = warp * 2 + g;            // batch within block (0..7)
    const int batch = blockIdx.x * 8 + bib;   // global batch
    const float* xrow = x + (size_t)batch * 512;

    // ---- weights into registers (row j of W_hh, packed into f32x2 pairs) ----
    unsigned long long Wp[8];
#pragma unroll
    for (int i = 0; i < 8; ++i)
        Wp[i] = pack2(Whh[j * 16 + 2 * i], Whh[j * 16 + 2 * i + 1]);
    const float wihj = Wih[j];
    const float bbj  = bih[j] + bhh[j];

    // ---- x chunk 0 -> smem, chunk 1 -> registers (prefetch) ----
    {
        float4 c0 = *(const float4*)(xrow + 0 * 64 + j * 4);
        *(float4*)&xbuf[bib][0][j * 4] = c0;
    }
    float4 pre = *(const float4*)(xrow + 1 * 64 + j * 4);

    // ---- h0 = 0 ----
    hbuf[bib][0][j] = 0.0f;
    hbuf[bib][1][j] = 0.0f;
    __syncwarp();

    float hj = 0.0f;

    // One recurrence step: read h from buffer PIN, write new h to buffer POUT.
#define RNN_STEP(PIN, POUT, XIDX)                                         \
    do {                                                                  \
        __syncwarp();                                                     \
        float xv = xc[(XIDX)];                                            \
        const ulonglong2* hp = (const ulonglong2*)hbuf[bib][(PIN)];       \
        ulonglong2 hA = hp[0];                                            \
        ulonglong2 hB = hp[1];                                            \
        unsigned long long a0 = mul2(hA.x, Wp[0]);                        \
        unsigned long long a1 = mul2(hA.y, Wp[1]);                        \
        a0 = fma2(hB.x, Wp[2], a0);                                       \
        a1 = fma2(hB.y, Wp[3], a1);                                       \
        ulonglong2 hC = hp[2];                                            \
        ulonglong2 hD = hp[3];                                            \
        a0 = fma2(hC.x, Wp[4], a0);                                       \
        a1 = fma2(hC.y, Wp[5], a1);                                       \
        a0 = fma2(hD.x, Wp[6], a0);                                       \
        a1 = fma2(hD.y, Wp[7], a1);                                       \
        a0 = add2(a0, a1);                                                \
        float z = fmaf(xv, wihj, bbj) + hsum2(a0);                        \
        hj = tanh_fast(z);                                                \
        hbuf[bib][(POUT)][j] = hj;                                        \
    } while (0)

#pragma unroll 1
    for (int c = 0; c < 8; ++c) {  // 8 chunks x 64 steps = 512
        const float* xc = xbuf[bib][c & 1];

        // first half: steps 0..31 of this chunk
#pragma unroll 8
        for (int t2 = 0; t2 < 32; t2 += 2) {
            RNN_STEP(0, 1, t2);
            RNN_STEP(1, 0, t2 + 1);
        }

        // mid-chunk: commit prefetched chunk c+1 to smem, start LDG for c+2.
        // (consumed only after future __syncwarp's; same-warp ordering is safe)
        *(float4*)&xbuf[bib][(c + 1) & 1][j * 4] = pre;
        if (c < 6)
            pre = *(const float4*)(xrow + (c + 2) * 64 + j * 4);

        // second half: steps 32..63
#pragma unroll 8
        for (int t2 = 32; t2 < 64; t2 += 2) {
            RNN_STEP(0, 1, t2);
            RNN_STEP(1, 0, t2 + 1);
        }
    }
#undef RNN_STEP

    // ---- epilogue: out[b] = sum_j h_j * Wfc[j] + bfc ----
    float v = hj * Wfc[j];
    v += __shfl_xor_sync(0xffffffffu, v, 8);
    v += __shfl_xor_sync(0xffffffffu, v, 4);
    v += __shfl_xor_sync(0xffffffffu, v, 2);
    v += __shfl_xor_sync(0xffffffffu, v, 1);
    if (j == 0)
        out[batch] = v + bfc[0];
}

extern "C" void kernel_launch(void* const* d_in, const int* in_sizes, int n_in,
                              void* d_out, int out_size) {
    const float* x   = (const float*)d_in[0];
    const float* Wih = (const float*)d_in[1];
    const float* Whh = (const float*)d_in[2];
    const float* bih = (const float*)d_in[3];
    const float* bhh = (const float*)d_in[4];
    const float* Wfc = (const float*)d_in[5];
    const float* bfc = (const float*)d_in[6];
    float* out = (float*)d_out;

    // 4096 batches / 8 per block = 512 blocks, 128 threads each
    rnn_kernel<<<512, 128>>>(x, Wih, Whh, bih, bhh, Wfc, bfc, out);
}